// round 12
// baseline (speedup 1.0000x reference)
#include <cuda_runtime.h>
#include <cstdint>

#define B_  4
#define S_  2048
#define F_  512
#define E_  512
#define H_  8
#define DH_ 64
#define ROWS_ (B_ * S_)

// Scratch, all pre-rounded to tf32:
//   g_Q, g_K : [B,H,S,DH]  with dh permuted within groups of 8 (pairing perm)
//   g_Vt     : [B,H,DH,S]  with key (S) permuted within groups of 8
__device__ float g_Q[B_ * H_ * S_ * DH_];
__device__ float g_K[B_ * H_ * S_ * DH_];
__device__ float g_Vt[B_ * H_ * DH_ * S_];

__device__ __forceinline__ uint32_t f2tf32(float f) {
    uint32_t u;
    asm("cvt.rna.tf32.f32 %0, %1;" : "=r"(u) : "f"(f));
    return u;
}
__device__ __forceinline__ float f2tf32f(float f) { return __uint_as_float(f2tf32(f)); }

__device__ __forceinline__ float fast_exp2(float x) {
    float y;
    asm("ex2.approx.f32 %0, %1;" : "=f"(y) : "f"(x));
    return y;
}

// Pairing permutation within a group of 8: k -> 2*(k&3) | (k>>2).
// Maps the mma fragment pair (k, k+4) to adjacent slots (2k, 2k+1).
__device__ __forceinline__ int pm8(int k) { return ((k & 3) << 1) | ((k >> 2) & 1); }

__device__ __forceinline__ void mma_tf32(float c[4],
                                         uint32_t a0, uint32_t a1, uint32_t a2, uint32_t a3,
                                         uint32_t b0, uint32_t b1) {
    asm volatile(
        "mma.sync.aligned.m16n8k8.row.col.f32.tf32.tf32.f32 "
        "{%0,%1,%2,%3},{%4,%5,%6,%7},{%8,%9},{%0,%1,%2,%3};\n"
        : "+f"(c[0]), "+f"(c[1]), "+f"(c[2]), "+f"(c[3])
        : "r"(a0), "r"(a1), "r"(a2), "r"(a3), "r"(b0), "r"(b1));
}

#define CP_ASYNC16(saddr, gptr) \
    asm volatile("cp.async.cg.shared.global [%0], [%1], 16;" :: "r"(saddr), "l"(gptr))
#define CP_COMMIT() asm volatile("cp.async.commit_group;" ::: "memory")
#define CP_WAIT0()  asm volatile("cp.async.wait_group 0;" ::: "memory")

// ---------------------------------------------------------------------------
// Kernel 1: fused QKV projection (SIMT tf32 HMMA).
// Epilogue pre-rounds to tf32 and writes the permuted scratch layouts.
// ---------------------------------------------------------------------------
__global__ __launch_bounds__(128) void qkv_kernel(
    const float* __restrict__ x, const float* __restrict__ etype,
    const float* __restrict__ Wq, const float* __restrict__ bq,
    const float* __restrict__ Wk, const float* __restrict__ bk,
    const float* __restrict__ Wv, const float* __restrict__ bv)
{
    const int z = blockIdx.z;
    const float* W    = (z == 0) ? Wq : (z == 1) ? Wk : Wv;
    const float* bias = (z == 0) ? bq : (z == 1) ? bk : bv;

    __shared__ float As[64][36];
    __shared__ float Bs[32][68];

    const int tid  = threadIdx.x;
    const int lane = tid & 31;
    const int warp = tid >> 5;
    const int g    = lane >> 2;
    const int tg   = lane & 3;
    const int wm   = warp * 16;
    const int row0 = blockIdx.x * 64;
    const int col0 = blockIdx.y * 64;

    float acc[8][4];
#pragma unroll
    for (int nt = 0; nt < 8; nt++)
#pragma unroll
        for (int i = 0; i < 4; i++) acc[nt][i] = 0.f;

    for (int k0 = 0; k0 < F_; k0 += 32) {
#pragma unroll
        for (int i = 0; i < 4; i++) {
            int u = tid + i * 128;
            int r = u >> 3, c = (u & 7) * 4;
            float4 v = *(const float4*)&x[(size_t)(row0 + r) * F_ + k0 + c];
            v.x = f2tf32f(v.x); v.y = f2tf32f(v.y);
            v.z = f2tf32f(v.z); v.w = f2tf32f(v.w);
            *(float4*)&As[r][c] = v;
        }
#pragma unroll
        for (int i = 0; i < 4; i++) {
            int u = tid + i * 128;
            int r = u >> 4, c = (u & 15) * 4;
            float4 v = *(const float4*)&W[(size_t)(k0 + r) * E_ + col0 + c];
            v.x = f2tf32f(v.x); v.y = f2tf32f(v.y);
            v.z = f2tf32f(v.z); v.w = f2tf32f(v.w);
            *(float4*)&Bs[r][c] = v;
        }
        __syncthreads();
#pragma unroll
        for (int ks = 0; ks < 4; ks++) {
            uint32_t a0 = __float_as_uint(As[wm + g    ][ks * 8 + tg    ]);
            uint32_t a1 = __float_as_uint(As[wm + g + 8][ks * 8 + tg    ]);
            uint32_t a2 = __float_as_uint(As[wm + g    ][ks * 8 + tg + 4]);
            uint32_t a3 = __float_as_uint(As[wm + g + 8][ks * 8 + tg + 4]);
#pragma unroll
            for (int nt = 0; nt < 8; nt++) {
                uint32_t b0 = __float_as_uint(Bs[ks * 8 + tg    ][nt * 8 + g]);
                uint32_t b1 = __float_as_uint(Bs[ks * 8 + tg + 4][nt * 8 + g]);
                mma_tf32(acc[nt], a0, a1, a2, a3, b0, b1);
            }
        }
        __syncthreads();
    }

    const int rg0 = row0 + wm + g;
    const int rg1 = rg0 + 8;
#pragma unroll
    for (int nt = 0; nt < 8; nt++) {
        int col = col0 + nt * 8 + tg * 2;
        float bv0 = bias[col], bv1 = bias[col + 1];
        float v00 = acc[nt][0] + bv0, v01 = acc[nt][1] + bv1;
        float v10 = acc[nt][2] + bv0, v11 = acc[nt][3] + bv1;
        if (z == 0) {
            float2 e0 = *(const float2*)&etype[(size_t)rg0 * E_ + col];
            float2 e1 = *(const float2*)&etype[(size_t)rg1 * E_ + col];
            v00 += e0.x; v01 += e0.y;
            v10 += e1.x; v11 += e1.y;
        }
        // Pre-round to tf32 (RNA) — attention kernel consumes raw bits.
        v00 = f2tf32f(v00); v01 = f2tf32f(v01);
        v10 = f2tf32f(v10); v11 = f2tf32f(v11);

        int hh = col >> 6, d = col & 63;
        int b0i = rg0 >> 11;
        int s0i = rg0 & (S_ - 1), s1i = rg1 & (S_ - 1);
        if (z != 2) {
            // Q/K: permute dh within 8 (mma k-dim pairing).
            float* o = (z == 0) ? g_Q : g_K;
            int dp0 = (d & ~7) | pm8(d & 7);
            int dp1 = (d & ~7) | pm8((d + 1) & 7);
            size_t r0b = (((size_t)b0i * H_ + hh) * S_ + s0i) * DH_;
            size_t r1b = (((size_t)b0i * H_ + hh) * S_ + s1i) * DH_;
            o[r0b + dp0] = v00; o[r0b + dp1] = v01;
            o[r1b + dp0] = v10; o[r1b + dp1] = v11;
        } else {
            // V^T [dh][key]: permute key within 8 (PV k-dim pairing).
            int sp0 = (s0i & ~7) | pm8(s0i & 7);
            int sp1 = (s1i & ~7) | pm8(s1i & 7);
            size_t base = (((size_t)b0i * H_ + hh) * DH_ + d) * S_;
            g_Vt[base + sp0]      = v00;
            g_Vt[base + S_ + sp0] = v01;
            g_Vt[base + sp1]      = v10;
            g_Vt[base + S_ + sp1] = v11;
        }
    }
}

// ---------------------------------------------------------------------------
// Kernel 2: flash attention, SIMT tf32 HMMA with paired LDS.64 fragments,
// cp.async tile loads, max-free softmax. One block per (b,h, 64-query tile).
// ---------------------------------------------------------------------------
__global__ __launch_bounds__(128) void attn_kernel(
    const int* __restrict__ mask, float* __restrict__ out)
{
    __shared__ float S1[64][68];   // Q stage -> K tile -> P tile
    __shared__ float S2[64][68];   // V^T tile [dh][key]
    __shared__ float kmf[64];

    const int tid  = threadIdx.x;
    const int lane = tid & 31;
    const int warp = tid >> 5;
    const int g    = lane >> 2;
    const int tg   = lane & 3;
    const int wm   = warp * 16;
    const int q0   = blockIdx.x * 64;
    const int bh   = blockIdx.y;
    const int b    = bh >> 3, h = bh & 7;

    const float* Qp = g_Q  + (size_t)bh * S_ * DH_;
    const float* Kp = g_K  + (size_t)bh * S_ * DH_;
    const float* Vp = g_Vt + (size_t)bh * DH_ * S_;
    const int*   mp = mask + b * S_;

    const int pc0 = pm8(tg * 2);       // permuted P-column slots for this thread
    const int pc1 = pm8(tg * 2 + 1);

    // ---- Stage Q via cp.async, build register fragments (paired loads) ----
#pragma unroll
    for (int i = 0; i < 8; i++) {
        int idx = tid + i * 128;
        int r = idx >> 4, c = (idx & 15) * 4;
        uint32_t sa = (uint32_t)__cvta_generic_to_shared(&S1[r][c]);
        CP_ASYNC16(sa, &Qp[(size_t)(q0 + r) * DH_ + c]);
    }
    CP_COMMIT(); CP_WAIT0();
    __syncthreads();

    uint32_t qf[8][4];
#pragma unroll
    for (int ks = 0; ks < 8; ks++) {
        float2 t0 = *(const float2*)&S1[wm + g    ][ks * 8 + 2 * tg];
        float2 t1 = *(const float2*)&S1[wm + g + 8][ks * 8 + 2 * tg];
        qf[ks][0] = __float_as_uint(t0.x);  // A[g][tg]
        qf[ks][2] = __float_as_uint(t0.y);  // A[g][tg+4]
        qf[ks][1] = __float_as_uint(t1.x);  // A[g+8][tg]
        qf[ks][3] = __float_as_uint(t1.y);  // A[g+8][tg+4]
    }
    __syncthreads();

    float l0 = 0.f, l1 = 0.f;
    float O[8][4];
#pragma unroll
    for (int nt = 0; nt < 8; nt++)
#pragma unroll
        for (int i = 0; i < 4; i++) O[nt][i] = 0.f;

    const float CEXP = 0.18033688f;     // 0.125 * log2(e)

    for (int kt = 0; kt < S_ / 64; kt++) {
        const int k0 = kt * 64;
        // K tile -> S1 [key][dh], V^T tile -> S2 [dh][key], via cp.async.
#pragma unroll
        for (int i = 0; i < 8; i++) {
            int idx = tid + i * 128;
            int r = idx >> 4, c = (idx & 15) * 4;
            uint32_t sa = (uint32_t)__cvta_generic_to_shared(&S1[r][c]);
            CP_ASYNC16(sa, &Kp[(size_t)(k0 + r) * DH_ + c]);
            uint32_t sv = (uint32_t)__cvta_generic_to_shared(&S2[r][c]);
            CP_ASYNC16(sv, &Vp[(size_t)r * S_ + k0 + c]);
        }
        if (tid < 64) kmf[tid] = (mp[k0 + tid] != 0) ? 1.f : 0.f;
        CP_COMMIT(); CP_WAIT0();
        __syncthreads();

        // ---- S = Q @ K^T  (m=query16/warp, n=key64, k=dh64) ----
        float sc[8][4];
#pragma unroll
        for (int nt = 0; nt < 8; nt++)
#pragma unroll
            for (int i = 0; i < 4; i++) sc[nt][i] = 0.f;
#pragma unroll
        for (int ks = 0; ks < 8; ks++) {
#pragma unroll
            for (int nt = 0; nt < 8; nt++) {
                float2 bb = *(const float2*)&S1[nt * 8 + g][ks * 8 + 2 * tg];
                mma_tf32(sc[nt], qf[ks][0], qf[ks][1], qf[ks][2], qf[ks][3],
                         __float_as_uint(bb.x), __float_as_uint(bb.y));
            }
        }

        __syncthreads();   // all warps done reading K before P overwrites S1

        // ---- Max-free softmax: p = e^(s/8), masked -> 0 ----
#pragma unroll
        for (int nt = 0; nt < 8; nt++) {
            int c = nt * 8 + tg * 2;
            float km0 = kmf[c], km1 = kmf[c + 1];
            float p0 = (km0 != 0.f) ? fast_exp2(sc[nt][0] * CEXP) : 0.f;
            float p1 = (km1 != 0.f) ? fast_exp2(sc[nt][1] * CEXP) : 0.f;
            float p2 = (km0 != 0.f) ? fast_exp2(sc[nt][2] * CEXP) : 0.f;
            float p3 = (km1 != 0.f) ? fast_exp2(sc[nt][3] * CEXP) : 0.f;
            l0 += p0 + p1;
            l1 += p2 + p3;
            // Store P with key-permuted columns (matches V^T key permutation).
            S1[wm + g    ][nt * 8 + pc0] = f2tf32f(p0);
            S1[wm + g    ][nt * 8 + pc1] = f2tf32f(p1);
            S1[wm + g + 8][nt * 8 + pc0] = f2tf32f(p2);
            S1[wm + g + 8][nt * 8 + pc1] = f2tf32f(p3);
        }
        __syncwarp();      // P rows are warp-private

        // ---- O += P @ V  (m=query16, n=dh64, k=key64) ----
#pragma unroll
        for (int k2 = 0; k2 < 8; k2++) {
            float2 t0 = *(const float2*)&S1[wm + g    ][k2 * 8 + 2 * tg];
            float2 t1 = *(const float2*)&S1[wm + g + 8][k2 * 8 + 2 * tg];
            uint32_t a0 = __float_as_uint(t0.x), a2 = __float_as_uint(t0.y);
            uint32_t a1 = __float_as_uint(t1.x), a3 = __float_as_uint(t1.y);
#pragma unroll
            for (int nt = 0; nt < 8; nt++) {
                float2 bb = *(const float2*)&S2[nt * 8 + g][k2 * 8 + 2 * tg];
                mma_tf32(O[nt], a0, a1, a2, a3,
                         __float_as_uint(bb.x), __float_as_uint(bb.y));
            }
        }
        __syncthreads();   // before next tile's cp.async overwrites S1/S2
    }

    // ---- Epilogue: reduce l over tg quad, normalize, query mask ----
    l0 += __shfl_xor_sync(0xffffffffu, l0, 1);
    l0 += __shfl_xor_sync(0xffffffffu, l0, 2);
    l1 += __shfl_xor_sync(0xffffffffu, l1, 1);
    l1 += __shfl_xor_sync(0xffffffffu, l1, 2);

    const int r0 = q0 + wm + g;
    const int r1 = r0 + 8;
    float inv0 = (mp[r0] != 0) ? 1.f / l0 : 0.f;
    float inv1 = (mp[r1] != 0) ? 1.f / l1 : 0.f;
    float* o0 = out + ((size_t)(b * S_ + r0) * E_) + h * DH_;
    float* o1 = out + ((size_t)(b * S_ + r1) * E_) + h * DH_;
#pragma unroll
    for (int nt = 0; nt < 8; nt++) {
        int c = nt * 8 + tg * 2;
        *(float2*)&o0[c] = make_float2(O[nt][0] * inv0, O[nt][1] * inv0);
        *(float2*)&o1[c] = make_float2(O[nt][2] * inv1, O[nt][3] * inv1);
    }
}

extern "C" void kernel_launch(void* const* d_in, const int* in_sizes, int n_in,
                              void* d_out, int out_size) {
    const float* x     = (const float*)d_in[0];
    const float* etype = (const float*)d_in[1];
    const int*   mask  = (const int*)d_in[2];
    const float* Wq    = (const float*)d_in[3];
    const float* bq    = (const float*)d_in[4];
    const float* Wk    = (const float*)d_in[5];
    const float* bk    = (const float*)d_in[6];
    const float* Wv    = (const float*)d_in[7];
    const float* bv    = (const float*)d_in[8];
    float* out = (float*)d_out;

    dim3 g1(ROWS_ / 64, E_ / 64, 3);
    qkv_kernel<<<g1, 128>>>(x, etype, Wq, bq, Wk, bk, Wv, bv);

    dim3 g2(S_ / 64, B_ * H_);
    attn_kernel<<<g2, 128>>>(mask, out);
}

// round 14
// speedup vs baseline: 1.0013x; 1.0013x over previous
#include <cuda_runtime.h>
#include <cstdint>

#define B_  4
#define S_  2048
#define F_  512
#define E_  512
#define H_  8
#define DH_ 64
#define ROWS_ (B_ * S_)

// Scratch, all pre-rounded to tf32:
//   g_Q, g_K : [B,H,S,DH]  with dh permuted within groups of 8 (pairing perm)
//   g_Vt     : [B,H,DH,S]  with key (S) permuted within groups of 8
__device__ float g_Q[B_ * H_ * S_ * DH_];
__device__ float g_K[B_ * H_ * S_ * DH_];
__device__ float g_Vt[B_ * H_ * DH_ * S_];

__device__ __forceinline__ uint32_t f2tf32(float f) {
    uint32_t u;
    asm("cvt.rna.tf32.f32 %0, %1;" : "=r"(u) : "f"(f));
    return u;
}
__device__ __forceinline__ float f2tf32f(float f) { return __uint_as_float(f2tf32(f)); }

__device__ __forceinline__ float fast_exp2(float x) {
    float y;
    asm("ex2.approx.f32 %0, %1;" : "=f"(y) : "f"(x));
    return y;
}

// Pairing permutation within a group of 8: k -> 2*(k&3) | (k>>2).
// Maps the mma fragment pair (k, k+4) to adjacent slots (2k, 2k+1).
__device__ __forceinline__ int pm8(int k) { return ((k & 3) << 1) | ((k >> 2) & 1); }

__device__ __forceinline__ void mma_tf32(float c[4],
                                         uint32_t a0, uint32_t a1, uint32_t a2, uint32_t a3,
                                         uint32_t b0, uint32_t b1) {
    asm volatile(
        "mma.sync.aligned.m16n8k8.row.col.f32.tf32.tf32.f32 "
        "{%0,%1,%2,%3},{%4,%5,%6,%7},{%8,%9},{%0,%1,%2,%3};\n"
        : "+f"(c[0]), "+f"(c[1]), "+f"(c[2]), "+f"(c[3])
        : "r"(a0), "r"(a1), "r"(a2), "r"(a3), "r"(b0), "r"(b1));
}

#define CP_ASYNC16(saddr, gptr) \
    asm volatile("cp.async.cg.shared.global [%0], [%1], 16;" :: "r"(saddr), "l"(gptr))
#define CP_COMMIT() asm volatile("cp.async.commit_group;" ::: "memory")
#define CP_WAIT0()  asm volatile("cp.async.wait_group 0;" ::: "memory")

// ---------------------------------------------------------------------------
// Kernel 1: fused QKV projection (SIMT tf32 HMMA).
// Epilogue pre-rounds to tf32 and writes the permuted scratch layouts.
// ---------------------------------------------------------------------------
__global__ __launch_bounds__(128) void qkv_kernel(
    const float* __restrict__ x, const float* __restrict__ etype,
    const float* __restrict__ Wq, const float* __restrict__ bq,
    const float* __restrict__ Wk, const float* __restrict__ bk,
    const float* __restrict__ Wv, const float* __restrict__ bv)
{
    const int z = blockIdx.z;
    const float* W    = (z == 0) ? Wq : (z == 1) ? Wk : Wv;
    const float* bias = (z == 0) ? bq : (z == 1) ? bk : bv;

    __shared__ float As[64][36];
    __shared__ float Bs[32][68];

    const int tid  = threadIdx.x;
    const int lane = tid & 31;
    const int warp = tid >> 5;
    const int g    = lane >> 2;
    const int tg   = lane & 3;
    const int wm   = warp * 16;
    const int row0 = blockIdx.x * 64;
    const int col0 = blockIdx.y * 64;

    float acc[8][4];
#pragma unroll
    for (int nt = 0; nt < 8; nt++)
#pragma unroll
        for (int i = 0; i < 4; i++) acc[nt][i] = 0.f;

    for (int k0 = 0; k0 < F_; k0 += 32) {
#pragma unroll
        for (int i = 0; i < 4; i++) {
            int u = tid + i * 128;
            int r = u >> 3, c = (u & 7) * 4;
            float4 v = *(const float4*)&x[(size_t)(row0 + r) * F_ + k0 + c];
            v.x = f2tf32f(v.x); v.y = f2tf32f(v.y);
            v.z = f2tf32f(v.z); v.w = f2tf32f(v.w);
            *(float4*)&As[r][c] = v;
        }
#pragma unroll
        for (int i = 0; i < 4; i++) {
            int u = tid + i * 128;
            int r = u >> 4, c = (u & 15) * 4;
            float4 v = *(const float4*)&W[(size_t)(k0 + r) * E_ + col0 + c];
            v.x = f2tf32f(v.x); v.y = f2tf32f(v.y);
            v.z = f2tf32f(v.z); v.w = f2tf32f(v.w);
            *(float4*)&Bs[r][c] = v;
        }
        __syncthreads();
#pragma unroll
        for (int ks = 0; ks < 4; ks++) {
            uint32_t a0 = __float_as_uint(As[wm + g    ][ks * 8 + tg    ]);
            uint32_t a1 = __float_as_uint(As[wm + g + 8][ks * 8 + tg    ]);
            uint32_t a2 = __float_as_uint(As[wm + g    ][ks * 8 + tg + 4]);
            uint32_t a3 = __float_as_uint(As[wm + g + 8][ks * 8 + tg + 4]);
#pragma unroll
            for (int nt = 0; nt < 8; nt++) {
                uint32_t b0 = __float_as_uint(Bs[ks * 8 + tg    ][nt * 8 + g]);
                uint32_t b1 = __float_as_uint(Bs[ks * 8 + tg + 4][nt * 8 + g]);
                mma_tf32(acc[nt], a0, a1, a2, a3, b0, b1);
            }
        }
        __syncthreads();
    }

    const int rg0 = row0 + wm + g;
    const int rg1 = rg0 + 8;
#pragma unroll
    for (int nt = 0; nt < 8; nt++) {
        int col = col0 + nt * 8 + tg * 2;
        float bv0 = bias[col], bv1 = bias[col + 1];
        float v00 = acc[nt][0] + bv0, v01 = acc[nt][1] + bv1;
        float v10 = acc[nt][2] + bv0, v11 = acc[nt][3] + bv1;
        if (z == 0) {
            float2 e0 = *(const float2*)&etype[(size_t)rg0 * E_ + col];
            float2 e1 = *(const float2*)&etype[(size_t)rg1 * E_ + col];
            v00 += e0.x; v01 += e0.y;
            v10 += e1.x; v11 += e1.y;
        }
        // Pre-round to tf32 (RNA) — attention kernel consumes raw bits.
        v00 = f2tf32f(v00); v01 = f2tf32f(v01);
        v10 = f2tf32f(v10); v11 = f2tf32f(v11);

        int hh = col >> 6, d = col & 63;
        int b0i = rg0 >> 11;
        int s0i = rg0 & (S_ - 1), s1i = rg1 & (S_ - 1);
        if (z != 2) {
            // Q/K: permute dh within 8 (mma k-dim pairing).
            float* o = (z == 0) ? g_Q : g_K;
            int dp0 = (d & ~7) | pm8(d & 7);
            int dp1 = (d & ~7) | pm8((d + 1) & 7);
            size_t r0b = (((size_t)b0i * H_ + hh) * S_ + s0i) * DH_;
            size_t r1b = (((size_t)b0i * H_ + hh) * S_ + s1i) * DH_;
            o[r0b + dp0] = v00; o[r0b + dp1] = v01;
            o[r1b + dp0] = v10; o[r1b + dp1] = v11;
        } else {
            // V^T [dh][key]: permute key within 8 (PV k-dim pairing).
            int sp0 = (s0i & ~7) | pm8(s0i & 7);
            int sp1 = (s1i & ~7) | pm8(s1i & 7);
            size_t base = (((size_t)b0i * H_ + hh) * DH_ + d) * S_;
            g_Vt[base + sp0]      = v00;
            g_Vt[base + S_ + sp0] = v01;
            g_Vt[base + sp1]      = v10;
            g_Vt[base + S_ + sp1] = v11;
        }
    }
}

// ---------------------------------------------------------------------------
// Kernel 2: flash attention, SIMT tf32 HMMA with paired LDS.64 fragments,
// cp.async tile loads, max-free softmax. One block per (b,h, 64-query tile).
// ---------------------------------------------------------------------------
__global__ __launch_bounds__(128) void attn_kernel(
    const int* __restrict__ mask, float* __restrict__ out)
{
    __shared__ float S1[64][68];   // Q stage -> K tile -> P tile
    __shared__ float S2[64][68];   // V^T tile [dh][key]
    __shared__ float kmf[64];

    const int tid  = threadIdx.x;
    const int lane = tid & 31;
    const int warp = tid >> 5;
    const int g    = lane >> 2;
    const int tg   = lane & 3;
    const int wm   = warp * 16;
    const int q0   = blockIdx.x * 64;
    const int bh   = blockIdx.y;
    const int b    = bh >> 3, h = bh & 7;

    const float* Qp = g_Q  + (size_t)bh * S_ * DH_;
    const float* Kp = g_K  + (size_t)bh * S_ * DH_;
    const float* Vp = g_Vt + (size_t)bh * DH_ * S_;
    const int*   mp = mask + b * S_;

    const int pc0 = pm8(tg * 2);       // permuted P-column slots for this thread
    const int pc1 = pm8(tg * 2 + 1);

    // ---- Stage Q via cp.async, build register fragments (paired loads) ----
#pragma unroll
    for (int i = 0; i < 8; i++) {
        int idx = tid + i * 128;
        int r = idx >> 4, c = (idx & 15) * 4;
        uint32_t sa = (uint32_t)__cvta_generic_to_shared(&S1[r][c]);
        CP_ASYNC16(sa, &Qp[(size_t)(q0 + r) * DH_ + c]);
    }
    CP_COMMIT(); CP_WAIT0();
    __syncthreads();

    uint32_t qf[8][4];
#pragma unroll
    for (int ks = 0; ks < 8; ks++) {
        float2 t0 = *(const float2*)&S1[wm + g    ][ks * 8 + 2 * tg];
        float2 t1 = *(const float2*)&S1[wm + g + 8][ks * 8 + 2 * tg];
        qf[ks][0] = __float_as_uint(t0.x);  // A[g][tg]
        qf[ks][2] = __float_as_uint(t0.y);  // A[g][tg+4]
        qf[ks][1] = __float_as_uint(t1.x);  // A[g+8][tg]
        qf[ks][3] = __float_as_uint(t1.y);  // A[g+8][tg+4]
    }
    __syncthreads();

    float l0 = 0.f, l1 = 0.f;
    float O[8][4];
#pragma unroll
    for (int nt = 0; nt < 8; nt++)
#pragma unroll
        for (int i = 0; i < 4; i++) O[nt][i] = 0.f;

    const float CEXP = 0.18033688f;     // 0.125 * log2(e)

    for (int kt = 0; kt < S_ / 64; kt++) {
        const int k0 = kt * 64;
        // K tile -> S1 [key][dh], V^T tile -> S2 [dh][key], via cp.async.
#pragma unroll
        for (int i = 0; i < 8; i++) {
            int idx = tid + i * 128;
            int r = idx >> 4, c = (idx & 15) * 4;
            uint32_t sa = (uint32_t)__cvta_generic_to_shared(&S1[r][c]);
            CP_ASYNC16(sa, &Kp[(size_t)(k0 + r) * DH_ + c]);
            uint32_t sv = (uint32_t)__cvta_generic_to_shared(&S2[r][c]);
            CP_ASYNC16(sv, &Vp[(size_t)r * S_ + k0 + c]);
        }
        if (tid < 64) kmf[tid] = (mp[k0 + tid] != 0) ? 1.f : 0.f;
        CP_COMMIT(); CP_WAIT0();
        __syncthreads();

        // ---- S = Q @ K^T  (m=query16/warp, n=key64, k=dh64) ----
        float sc[8][4];
#pragma unroll
        for (int nt = 0; nt < 8; nt++)
#pragma unroll
            for (int i = 0; i < 4; i++) sc[nt][i] = 0.f;
#pragma unroll
        for (int ks = 0; ks < 8; ks++) {
#pragma unroll
            for (int nt = 0; nt < 8; nt++) {
                float2 bb = *(const float2*)&S1[nt * 8 + g][ks * 8 + 2 * tg];
                mma_tf32(sc[nt], qf[ks][0], qf[ks][1], qf[ks][2], qf[ks][3],
                         __float_as_uint(bb.x), __float_as_uint(bb.y));
            }
        }

        __syncthreads();   // all warps done reading K before P overwrites S1

        // ---- Max-free softmax: p = e^(s/8), masked -> 0 ----
#pragma unroll
        for (int nt = 0; nt < 8; nt++) {
            int c = nt * 8 + tg * 2;
            float km0 = kmf[c], km1 = kmf[c + 1];
            float p0 = (km0 != 0.f) ? fast_exp2(sc[nt][0] * CEXP) : 0.f;
            float p1 = (km1 != 0.f) ? fast_exp2(sc[nt][1] * CEXP) : 0.f;
            float p2 = (km0 != 0.f) ? fast_exp2(sc[nt][2] * CEXP) : 0.f;
            float p3 = (km1 != 0.f) ? fast_exp2(sc[nt][3] * CEXP) : 0.f;
            l0 += p0 + p1;
            l1 += p2 + p3;
            // Store P with key-permuted columns (matches V^T key permutation).
            S1[wm + g    ][nt * 8 + pc0] = f2tf32f(p0);
            S1[wm + g    ][nt * 8 + pc1] = f2tf32f(p1);
            S1[wm + g + 8][nt * 8 + pc0] = f2tf32f(p2);
            S1[wm + g + 8][nt * 8 + pc1] = f2tf32f(p3);
        }
        __syncwarp();      // P rows are warp-private

        // ---- O += P @ V  (m=query16, n=dh64, k=key64) ----
#pragma unroll
        for (int k2 = 0; k2 < 8; k2++) {
            float2 t0 = *(const float2*)&S1[wm + g    ][k2 * 8 + 2 * tg];
            float2 t1 = *(const float2*)&S1[wm + g + 8][k2 * 8 + 2 * tg];
            uint32_t a0 = __float_as_uint(t0.x), a2 = __float_as_uint(t0.y);
            uint32_t a1 = __float_as_uint(t1.x), a3 = __float_as_uint(t1.y);
#pragma unroll
            for (int nt = 0; nt < 8; nt++) {
                float2 bb = *(const float2*)&S2[nt * 8 + g][k2 * 8 + 2 * tg];
                mma_tf32(O[nt], a0, a1, a2, a3,
                         __float_as_uint(bb.x), __float_as_uint(bb.y));
            }
        }
        __syncthreads();   // before next tile's cp.async overwrites S1/S2
    }

    // ---- Epilogue: reduce l over tg quad, normalize, query mask ----
    l0 += __shfl_xor_sync(0xffffffffu, l0, 1);
    l0 += __shfl_xor_sync(0xffffffffu, l0, 2);
    l1 += __shfl_xor_sync(0xffffffffu, l1, 1);
    l1 += __shfl_xor_sync(0xffffffffu, l1, 2);

    const int r0 = q0 + wm + g;
    const int r1 = r0 + 8;
    float inv0 = (mp[r0] != 0) ? 1.f / l0 : 0.f;
    float inv1 = (mp[r1] != 0) ? 1.f / l1 : 0.f;
    float* o0 = out + ((size_t)(b * S_ + r0) * E_) + h * DH_;
    float* o1 = out + ((size_t)(b * S_ + r1) * E_) + h * DH_;
#pragma unroll
    for (int nt = 0; nt < 8; nt++) {
        int c = nt * 8 + tg * 2;
        *(float2*)&o0[c] = make_float2(O[nt][0] * inv0, O[nt][1] * inv0);
        *(float2*)&o1[c] = make_float2(O[nt][2] * inv1, O[nt][3] * inv1);
    }
}

extern "C" void kernel_launch(void* const* d_in, const int* in_sizes, int n_in,
                              void* d_out, int out_size) {
    const float* x     = (const float*)d_in[0];
    const float* etype = (const float*)d_in[1];
    const int*   mask  = (const int*)d_in[2];
    const float* Wq    = (const float*)d_in[3];
    const float* bq    = (const float*)d_in[4];
    const float* Wk    = (const float*)d_in[5];
    const float* bk    = (const float*)d_in[6];
    const float* Wv    = (const float*)d_in[7];
    const float* bv    = (const float*)d_in[8];
    float* out = (float*)d_out;

    dim3 g1(ROWS_ / 64, E_ / 64, 3);
    qkv_kernel<<<g1, 128>>>(x, etype, Wq, bq, Wk, bk, Wv, bv);

    dim3 g2(S_ / 64, B_ * H_);
    attn_kernel<<<g2, 128>>>(mask, out);
}

// round 16
// speedup vs baseline: 1.0020x; 1.0007x over previous
#include <cuda_runtime.h>
#include <cstdint>

#define B_  4
#define S_  2048
#define F_  512
#define E_  512
#define H_  8
#define DH_ 64
#define ROWS_ (B_ * S_)

// Scratch, all pre-rounded to tf32:
//   g_Q, g_K : [B,H,S,DH]  with dh permuted within groups of 8 (pairing perm)
//   g_Vt     : [B,H,DH,S]  with key (S) permuted within groups of 8
__device__ float g_Q[B_ * H_ * S_ * DH_];
__device__ float g_K[B_ * H_ * S_ * DH_];
__device__ float g_Vt[B_ * H_ * DH_ * S_];

__device__ __forceinline__ uint32_t f2tf32(float f) {
    uint32_t u;
    asm("cvt.rna.tf32.f32 %0, %1;" : "=r"(u) : "f"(f));
    return u;
}
__device__ __forceinline__ float f2tf32f(float f) { return __uint_as_float(f2tf32(f)); }

__device__ __forceinline__ float fast_exp2(float x) {
    float y;
    asm("ex2.approx.f32 %0, %1;" : "=f"(y) : "f"(x));
    return y;
}

// Pairing permutation within a group of 8: k -> 2*(k&3) | (k>>2).
// Maps the mma fragment pair (k, k+4) to adjacent slots (2k, 2k+1).
__device__ __forceinline__ int pm8(int k) { return ((k & 3) << 1) | ((k >> 2) & 1); }

__device__ __forceinline__ void mma_tf32(float c[4],
                                         uint32_t a0, uint32_t a1, uint32_t a2, uint32_t a3,
                                         uint32_t b0, uint32_t b1) {
    asm volatile(
        "mma.sync.aligned.m16n8k8.row.col.f32.tf32.tf32.f32 "
        "{%0,%1,%2,%3},{%4,%5,%6,%7},{%8,%9},{%0,%1,%2,%3};\n"
        : "+f"(c[0]), "+f"(c[1]), "+f"(c[2]), "+f"(c[3])
        : "r"(a0), "r"(a1), "r"(a2), "r"(a3), "r"(b0), "r"(b1));
}

#define CP_ASYNC16(saddr, gptr) \
    asm volatile("cp.async.cg.shared.global [%0], [%1], 16;" :: "r"(saddr), "l"(gptr))
#define CP_COMMIT() asm volatile("cp.async.commit_group;" ::: "memory")
#define CP_WAIT0()  asm volatile("cp.async.wait_group 0;" ::: "memory")

// ---------------------------------------------------------------------------
// Kernel 1: fused QKV projection (SIMT tf32 HMMA).
// Epilogue pre-rounds to tf32 and writes the permuted scratch layouts.
// ---------------------------------------------------------------------------
__global__ __launch_bounds__(128) void qkv_kernel(
    const float* __restrict__ x, const float* __restrict__ etype,
    const float* __restrict__ Wq, const float* __restrict__ bq,
    const float* __restrict__ Wk, const float* __restrict__ bk,
    const float* __restrict__ Wv, const float* __restrict__ bv)
{
    const int z = blockIdx.z;
    const float* W    = (z == 0) ? Wq : (z == 1) ? Wk : Wv;
    const float* bias = (z == 0) ? bq : (z == 1) ? bk : bv;

    __shared__ float As[64][36];
    __shared__ float Bs[32][68];

    const int tid  = threadIdx.x;
    const int lane = tid & 31;
    const int warp = tid >> 5;
    const int g    = lane >> 2;
    const int tg   = lane & 3;
    const int wm   = warp * 16;
    const int row0 = blockIdx.x * 64;
    const int col0 = blockIdx.y * 64;

    float acc[8][4];
#pragma unroll
    for (int nt = 0; nt < 8; nt++)
#pragma unroll
        for (int i = 0; i < 4; i++) acc[nt][i] = 0.f;

    for (int k0 = 0; k0 < F_; k0 += 32) {
#pragma unroll
        for (int i = 0; i < 4; i++) {
            int u = tid + i * 128;
            int r = u >> 3, c = (u & 7) * 4;
            float4 v = *(const float4*)&x[(size_t)(row0 + r) * F_ + k0 + c];
            v.x = f2tf32f(v.x); v.y = f2tf32f(v.y);
            v.z = f2tf32f(v.z); v.w = f2tf32f(v.w);
            *(float4*)&As[r][c] = v;
        }
#pragma unroll
        for (int i = 0; i < 4; i++) {
            int u = tid + i * 128;
            int r = u >> 4, c = (u & 15) * 4;
            float4 v = *(const float4*)&W[(size_t)(k0 + r) * E_ + col0 + c];
            v.x = f2tf32f(v.x); v.y = f2tf32f(v.y);
            v.z = f2tf32f(v.z); v.w = f2tf32f(v.w);
            *(float4*)&Bs[r][c] = v;
        }
        __syncthreads();
#pragma unroll
        for (int ks = 0; ks < 4; ks++) {
            uint32_t a0 = __float_as_uint(As[wm + g    ][ks * 8 + tg    ]);
            uint32_t a1 = __float_as_uint(As[wm + g + 8][ks * 8 + tg    ]);
            uint32_t a2 = __float_as_uint(As[wm + g    ][ks * 8 + tg + 4]);
            uint32_t a3 = __float_as_uint(As[wm + g + 8][ks * 8 + tg + 4]);
#pragma unroll
            for (int nt = 0; nt < 8; nt++) {
                uint32_t b0 = __float_as_uint(Bs[ks * 8 + tg    ][nt * 8 + g]);
                uint32_t b1 = __float_as_uint(Bs[ks * 8 + tg + 4][nt * 8 + g]);
                mma_tf32(acc[nt], a0, a1, a2, a3, b0, b1);
            }
        }
        __syncthreads();
    }

    const int rg0 = row0 + wm + g;
    const int rg1 = rg0 + 8;
#pragma unroll
    for (int nt = 0; nt < 8; nt++) {
        int col = col0 + nt * 8 + tg * 2;
        float bv0 = bias[col], bv1 = bias[col + 1];
        float v00 = acc[nt][0] + bv0, v01 = acc[nt][1] + bv1;
        float v10 = acc[nt][2] + bv0, v11 = acc[nt][3] + bv1;
        if (z == 0) {
            float2 e0 = *(const float2*)&etype[(size_t)rg0 * E_ + col];
            float2 e1 = *(const float2*)&etype[(size_t)rg1 * E_ + col];
            v00 += e0.x; v01 += e0.y;
            v10 += e1.x; v11 += e1.y;
        }
        // Pre-round to tf32 (RNA) — attention kernel consumes raw bits.
        v00 = f2tf32f(v00); v01 = f2tf32f(v01);
        v10 = f2tf32f(v10); v11 = f2tf32f(v11);

        int hh = col >> 6, d = col & 63;
        int b0i = rg0 >> 11;
        int s0i = rg0 & (S_ - 1), s1i = rg1 & (S_ - 1);
        if (z != 2) {
            // Q/K: permute dh within 8 (mma k-dim pairing).
            float* o = (z == 0) ? g_Q : g_K;
            int dp0 = (d & ~7) | pm8(d & 7);
            int dp1 = (d & ~7) | pm8((d + 1) & 7);
            size_t r0b = (((size_t)b0i * H_ + hh) * S_ + s0i) * DH_;
            size_t r1b = (((size_t)b0i * H_ + hh) * S_ + s1i) * DH_;
            o[r0b + dp0] = v00; o[r0b + dp1] = v01;
            o[r1b + dp0] = v10; o[r1b + dp1] = v11;
        } else {
            // V^T [dh][key]: permute key within 8 (PV k-dim pairing).
            int sp0 = (s0i & ~7) | pm8(s0i & 7);
            int sp1 = (s1i & ~7) | pm8(s1i & 7);
            size_t base = (((size_t)b0i * H_ + hh) * DH_ + d) * S_;
            g_Vt[base + sp0]      = v00;
            g_Vt[base + S_ + sp0] = v01;
            g_Vt[base + sp1]      = v10;
            g_Vt[base + S_ + sp1] = v11;
        }
    }
}

// ---------------------------------------------------------------------------
// Kernel 2: flash attention, SIMT tf32 HMMA with paired LDS.64 fragments,
// cp.async tile loads, max-free softmax. One block per (b,h, 64-query tile).
// ---------------------------------------------------------------------------
__global__ __launch_bounds__(128) void attn_kernel(
    const int* __restrict__ mask, float* __restrict__ out)
{
    __shared__ float S1[64][68];   // Q stage -> K tile -> P tile
    __shared__ float S2[64][68];   // V^T tile [dh][key]
    __shared__ float kmf[64];

    const int tid  = threadIdx.x;
    const int lane = tid & 31;
    const int warp = tid >> 5;
    const int g    = lane >> 2;
    const int tg   = lane & 3;
    const int wm   = warp * 16;
    const int q0   = blockIdx.x * 64;
    const int bh   = blockIdx.y;
    const int b    = bh >> 3, h = bh & 7;

    const float* Qp = g_Q  + (size_t)bh * S_ * DH_;
    const float* Kp = g_K  + (size_t)bh * S_ * DH_;
    const float* Vp = g_Vt + (size_t)bh * DH_ * S_;
    const int*   mp = mask + b * S_;

    const int pc0 = pm8(tg * 2);       // permuted P-column slots for this thread
    const int pc1 = pm8(tg * 2 + 1);

    // ---- Stage Q via cp.async, build register fragments (paired loads) ----
#pragma unroll
    for (int i = 0; i < 8; i++) {
        int idx = tid + i * 128;
        int r = idx >> 4, c = (idx & 15) * 4;
        uint32_t sa = (uint32_t)__cvta_generic_to_shared(&S1[r][c]);
        CP_ASYNC16(sa, &Qp[(size_t)(q0 + r) * DH_ + c]);
    }
    CP_COMMIT(); CP_WAIT0();
    __syncthreads();

    uint32_t qf[8][4];
#pragma unroll
    for (int ks = 0; ks < 8; ks++) {
        float2 t0 = *(const float2*)&S1[wm + g    ][ks * 8 + 2 * tg];
        float2 t1 = *(const float2*)&S1[wm + g + 8][ks * 8 + 2 * tg];
        qf[ks][0] = __float_as_uint(t0.x);  // A[g][tg]
        qf[ks][2] = __float_as_uint(t0.y);  // A[g][tg+4]
        qf[ks][1] = __float_as_uint(t1.x);  // A[g+8][tg]
        qf[ks][3] = __float_as_uint(t1.y);  // A[g+8][tg+4]
    }
    __syncthreads();

    float l0 = 0.f, l1 = 0.f;
    float O[8][4];
#pragma unroll
    for (int nt = 0; nt < 8; nt++)
#pragma unroll
        for (int i = 0; i < 4; i++) O[nt][i] = 0.f;

    const float CEXP = 0.18033688f;     // 0.125 * log2(e)

    for (int kt = 0; kt < S_ / 64; kt++) {
        const int k0 = kt * 64;
        // K tile -> S1 [key][dh], V^T tile -> S2 [dh][key], via cp.async.
#pragma unroll
        for (int i = 0; i < 8; i++) {
            int idx = tid + i * 128;
            int r = idx >> 4, c = (idx & 15) * 4;
            uint32_t sa = (uint32_t)__cvta_generic_to_shared(&S1[r][c]);
            CP_ASYNC16(sa, &Kp[(size_t)(k0 + r) * DH_ + c]);
            uint32_t sv = (uint32_t)__cvta_generic_to_shared(&S2[r][c]);
            CP_ASYNC16(sv, &Vp[(size_t)r * S_ + k0 + c]);
        }
        if (tid < 64) kmf[tid] = (mp[k0 + tid] != 0) ? 1.f : 0.f;
        CP_COMMIT(); CP_WAIT0();
        __syncthreads();

        // ---- S = Q @ K^T  (m=query16/warp, n=key64, k=dh64) ----
        float sc[8][4];
#pragma unroll
        for (int nt = 0; nt < 8; nt++)
#pragma unroll
            for (int i = 0; i < 4; i++) sc[nt][i] = 0.f;
#pragma unroll
        for (int ks = 0; ks < 8; ks++) {
#pragma unroll
            for (int nt = 0; nt < 8; nt++) {
                float2 bb = *(const float2*)&S1[nt * 8 + g][ks * 8 + 2 * tg];
                mma_tf32(sc[nt], qf[ks][0], qf[ks][1], qf[ks][2], qf[ks][3],
                         __float_as_uint(bb.x), __float_as_uint(bb.y));
            }
        }

        __syncthreads();   // all warps done reading K before P overwrites S1

        // ---- Max-free softmax: p = e^(s/8), masked -> 0 ----
#pragma unroll
        for (int nt = 0; nt < 8; nt++) {
            int c = nt * 8 + tg * 2;
            float km0 = kmf[c], km1 = kmf[c + 1];
            float p0 = (km0 != 0.f) ? fast_exp2(sc[nt][0] * CEXP) : 0.f;
            float p1 = (km1 != 0.f) ? fast_exp2(sc[nt][1] * CEXP) : 0.f;
            float p2 = (km0 != 0.f) ? fast_exp2(sc[nt][2] * CEXP) : 0.f;
            float p3 = (km1 != 0.f) ? fast_exp2(sc[nt][3] * CEXP) : 0.f;
            l0 += p0 + p1;
            l1 += p2 + p3;
            // Store P with key-permuted columns (matches V^T key permutation).
            S1[wm + g    ][nt * 8 + pc0] = f2tf32f(p0);
            S1[wm + g    ][nt * 8 + pc1] = f2tf32f(p1);
            S1[wm + g + 8][nt * 8 + pc0] = f2tf32f(p2);
            S1[wm + g + 8][nt * 8 + pc1] = f2tf32f(p3);
        }
        __syncwarp();      // P rows are warp-private

        // ---- O += P @ V  (m=query16, n=dh64, k=key64) ----
#pragma unroll
        for (int k2 = 0; k2 < 8; k2++) {
            float2 t0 = *(const float2*)&S1[wm + g    ][k2 * 8 + 2 * tg];
            float2 t1 = *(const float2*)&S1[wm + g + 8][k2 * 8 + 2 * tg];
            uint32_t a0 = __float_as_uint(t0.x), a2 = __float_as_uint(t0.y);
            uint32_t a1 = __float_as_uint(t1.x), a3 = __float_as_uint(t1.y);
#pragma unroll
            for (int nt = 0; nt < 8; nt++) {
                float2 bb = *(const float2*)&S2[nt * 8 + g][k2 * 8 + 2 * tg];
                mma_tf32(O[nt], a0, a1, a2, a3,
                         __float_as_uint(bb.x), __float_as_uint(bb.y));
            }
        }
        __syncthreads();   // before next tile's cp.async overwrites S1/S2
    }

    // ---- Epilogue: reduce l over tg quad, normalize, query mask ----
    l0 += __shfl_xor_sync(0xffffffffu, l0, 1);
    l0 += __shfl_xor_sync(0xffffffffu, l0, 2);
    l1 += __shfl_xor_sync(0xffffffffu, l1, 1);
    l1 += __shfl_xor_sync(0xffffffffu, l1, 2);

    const int r0 = q0 + wm + g;
    const int r1 = r0 + 8;
    float inv0 = (mp[r0] != 0) ? 1.f / l0 : 0.f;
    float inv1 = (mp[r1] != 0) ? 1.f / l1 : 0.f;
    float* o0 = out + ((size_t)(b * S_ + r0) * E_) + h * DH_;
    float* o1 = out + ((size_t)(b * S_ + r1) * E_) + h * DH_;
#pragma unroll
    for (int nt = 0; nt < 8; nt++) {
        int c = nt * 8 + tg * 2;
        *(float2*)&o0[c] = make_float2(O[nt][0] * inv0, O[nt][1] * inv0);
        *(float2*)&o1[c] = make_float2(O[nt][2] * inv1, O[nt][3] * inv1);
    }
}

extern "C" void kernel_launch(void* const* d_in, const int* in_sizes, int n_in,
                              void* d_out, int out_size) {
    const float* x     = (const float*)d_in[0];
    const float* etype = (const float*)d_in[1];
    const int*   mask  = (const int*)d_in[2];
    const float* Wq    = (const float*)d_in[3];
    const float* bq    = (const float*)d_in[4];
    const float* Wk    = (const float*)d_in[5];
    const float* bk    = (const float*)d_in[6];
    const float* Wv    = (const float*)d_in[7];
    const float* bv    = (const float*)d_in[8];
    float* out = (float*)d_out;

    dim3 g1(ROWS_ / 64, E_ / 64, 3);
    qkv_kernel<<<g1, 128>>>(x, etype, Wq, bq, Wk, bk, Wv, bv);

    dim3 g2(S_ / 64, B_ * H_);
    attn_kernel<<<g2, 128>>>(mask, out);
}